// round 2
// baseline (speedup 1.0000x reference)
#include <cuda_runtime.h>
#include <cuda_bf16.h>
#include <math.h>

// Problem constants
#define BB 4
#define TT 2048
#define CC 2048
#define HH 16
#define HD 128
#define NTOK (BB*TT)          // 8192
#define C4 (4*CC)             // 8192
#define QKVN (3*CC)           // 6144

// ---------------- scratch (device globals; no allocation allowed) ------------
__device__ float g_h1  [(size_t)NTOK * CC];     // ln1 out
__device__ float g_qkv [(size_t)NTOK * QKVN];   // q|k|v concat, col = s*2048 + h*128 + d
__device__ float g_attn[(size_t)NTOK * CC];     // attention out (heads concat)
__device__ float g_x1  [(size_t)NTOK * CC];     // x + proj
__device__ float g_h2  [(size_t)NTOK * CC];     // ln2 out
__device__ float g_ffn [(size_t)NTOK * C4];     // gelu(h2@W1+b1)
__device__ float g_wqkv[(size_t)CC * QKVN];     // packed qkv weights [C, 3C]

// ---------------- layernorm ---------------------------------------------------
__global__ void ln_kernel(const float* __restrict__ x, const float* __restrict__ g,
                          const float* __restrict__ beta, float* __restrict__ out) {
    int t = blockIdx.x;
    const float* xr = x + (size_t)t * CC;
    float* orow = out + (size_t)t * CC;
    float s = 0.f, s2 = 0.f;
    for (int i = threadIdx.x; i < CC; i += 256) { float v = xr[i]; s += v; s2 += v * v; }
    __shared__ float red0[8], red1[8];
    #pragma unroll
    for (int o = 16; o; o >>= 1) {
        s  += __shfl_xor_sync(0xffffffffu, s,  o);
        s2 += __shfl_xor_sync(0xffffffffu, s2, o);
    }
    int w = threadIdx.x >> 5, l = threadIdx.x & 31;
    if (l == 0) { red0[w] = s; red1[w] = s2; }
    __syncthreads();
    if (w == 0) {
        s  = (l < 8) ? red0[l] : 0.f;
        s2 = (l < 8) ? red1[l] : 0.f;
        #pragma unroll
        for (int o = 4; o; o >>= 1) {
            s  += __shfl_xor_sync(0xffffffffu, s,  o);
            s2 += __shfl_xor_sync(0xffffffffu, s2, o);
        }
        if (l == 0) { red0[0] = s; red1[0] = s2; }
    }
    __syncthreads();
    float mean = red0[0] * (1.f / CC);
    float var  = red1[0] * (1.f / CC) - mean * mean;
    float rstd = rsqrtf(var + 1e-5f);
    for (int i = threadIdx.x; i < CC; i += 256)
        orow[i] = (xr[i] - mean) * rstd * g[i] + beta[i];
}

// ---------------- pack Wq/Wk/Wv -> [C, 3C] ------------------------------------
__global__ void pack_qkv_kernel(const float* __restrict__ Wq, const float* __restrict__ Wk,
                                const float* __restrict__ Wv, float* __restrict__ Wcat) {
    int idx = blockIdx.x * blockDim.x + threadIdx.x;   // (s, h, c, d)
    if (idx >= 3 * CC * CC) return;
    int d = idx & 127;
    int c = (idx >> 7) & 2047;
    int h = (idx >> 18) & 15;
    int s = idx >> 22;
    const float* W = (s == 0) ? Wq : (s == 1) ? Wk : Wv;
    Wcat[(size_t)c * QKVN + s * CC + h * HD + d] = W[((size_t)h * CC + c) * HD + d];
}

// ---------------- generic GEMM ------------------------------------------------
__device__ __forceinline__ float gelu_exact(float v) {
    return 0.5f * v * (1.0f + erff(v * 0.7071067811865475f));
}

template<bool BIAS, bool RES, bool GELU>
__global__ __launch_bounds__(256)
void gemm_kernel(const float* __restrict__ A, const float* __restrict__ B,
                 const float* __restrict__ bias, const float* __restrict__ res,
                 float* __restrict__ C, int M, int N, int K) {
    __shared__ float As[8][132];   // As[k][m], padded
    __shared__ float Bs[8][128];

    const int tid = threadIdx.x;
    const int bm = blockIdx.y * 128;
    const int bn = blockIdx.x * 128;

    const int a_row = tid >> 1;
    const int a_col = (tid & 1) * 4;
    const int b_row = tid >> 5;
    const int b_col = (tid & 31) * 4;

    const float* Aptr = A + (size_t)(bm + a_row) * K + a_col;
    const float* Bptr = B + (size_t)b_row * N + bn + b_col;

    const int tx = tid & 15, ty = tid >> 4;
    const int cm = ty * 8, cn = tx * 8;

    float acc[8][8];
    #pragma unroll
    for (int i = 0; i < 8; i++)
        #pragma unroll
        for (int j = 0; j < 8; j++) acc[i][j] = 0.f;

    for (int k0 = 0; k0 < K; k0 += 8) {
        float4 av = *(const float4*)Aptr;
        float4 bv = *(const float4*)Bptr;
        __syncthreads();
        As[a_col + 0][a_row] = av.x;
        As[a_col + 1][a_row] = av.y;
        As[a_col + 2][a_row] = av.z;
        As[a_col + 3][a_row] = av.w;
        *(float4*)&Bs[b_row][b_col] = bv;
        __syncthreads();
        #pragma unroll
        for (int kk = 0; kk < 8; kk++) {
            float a[8], b[8];
            *(float4*)(a)     = *(const float4*)&As[kk][cm];
            *(float4*)(a + 4) = *(const float4*)&As[kk][cm + 4];
            *(float4*)(b)     = *(const float4*)&Bs[kk][cn];
            *(float4*)(b + 4) = *(const float4*)&Bs[kk][cn + 4];
            #pragma unroll
            for (int i = 0; i < 8; i++)
                #pragma unroll
                for (int j = 0; j < 8; j++) acc[i][j] += a[i] * b[j];
        }
        Aptr += 8;
        Bptr += (size_t)8 * N;
    }

    #pragma unroll
    for (int i = 0; i < 8; i++) {
        size_t off = (size_t)(bm + cm + i) * N + bn + cn;
        #pragma unroll
        for (int j0 = 0; j0 < 8; j0 += 4) {
            float4 v;
            v.x = acc[i][j0 + 0]; v.y = acc[i][j0 + 1];
            v.z = acc[i][j0 + 2]; v.w = acc[i][j0 + 3];
            if (BIAS) {
                float4 bb = *(const float4*)&bias[bn + cn + j0];
                v.x += bb.x; v.y += bb.y; v.z += bb.z; v.w += bb.w;
            }
            if (GELU) {
                v.x = gelu_exact(v.x); v.y = gelu_exact(v.y);
                v.z = gelu_exact(v.z); v.w = gelu_exact(v.w);
            }
            if (RES) {
                float4 rr = *(const float4*)&res[off + j0];
                v.x += rr.x; v.y += rr.y; v.z += rr.z; v.w += rr.w;
            }
            *(float4*)&C[off + j0] = v;
        }
    }
}

// ---------------- causal flash attention --------------------------------------
// block: 128 threads, 64-query tile; grid (T/64, B*H)
__global__ __launch_bounds__(128)
void attention_kernel(const float* __restrict__ qkv, float* __restrict__ out) {
    extern __shared__ float sm[];
    float* Qt  = sm;               // [128][65]  (d-major, padded)
    float* Kt  = Qt + 128 * 65;    // [128][65]
    float* Vs  = Kt + 128 * 65;    // [64][128]
    float* Ss  = Vs + 64 * 128;    // [64][65]
    float* m_s = Ss + 64 * 65;     // [64]
    float* l_s = m_s + 64;         // [64]
    float* c_s = l_s + 64;         // [64]

    const int tid = threadIdx.x;
    const int bh = blockIdx.y;
    const int b  = bh >> 4, h = bh & 15;
    const int qb = blockIdx.x;
    const int q0 = qb * 64;
    const float scale = 0.08838834764831845f;   // 1/sqrt(128)

    const size_t base = ((size_t)b * TT) * QKVN + h * HD;

    for (int idx = tid; idx < 64 * 128; idx += 128) {
        int r = idx >> 7, d = idx & 127;
        Qt[d * 65 + r] = qkv[base + (size_t)(q0 + r) * QKVN + d] * scale;
    }
    if (tid < 64) { m_s[tid] = -1e30f; l_s[tid] = 0.f; }

    float O[4][16];
    #pragma unroll
    for (int i = 0; i < 4; i++)
        #pragma unroll
        for (int n = 0; n < 16; n++) O[i][n] = 0.f;

    const int ty = tid >> 3, tx = tid & 7;
    const int r0 = ty * 4;

    for (int kb = 0; kb <= qb; kb++) {
        const int k0 = kb * 64;
        __syncthreads();   // protect Kt/Vs/Ss from previous iteration readers
        for (int idx = tid; idx < 64 * 128; idx += 128) {
            int c = idx >> 7, d = idx & 127;
            size_t tk = base + (size_t)(k0 + c) * QKVN;
            Kt[d * 65 + c]  = qkv[tk + CC + d];         // K
            Vs[c * 128 + d] = qkv[tk + 2 * CC + d];     // V
        }
        __syncthreads();

        // S = Q K^T   (rows r0..r0+3, cols tx + 8j)
        float sacc[4][8];
        #pragma unroll
        for (int i = 0; i < 4; i++)
            #pragma unroll
            for (int j = 0; j < 8; j++) sacc[i][j] = 0.f;
        #pragma unroll 4
        for (int d = 0; d < 128; d++) {
            float a[4], kv[8];
            #pragma unroll
            for (int i = 0; i < 4; i++) a[i] = Qt[d * 65 + r0 + i];
            #pragma unroll
            for (int j = 0; j < 8; j++) kv[j] = Kt[d * 65 + tx + 8 * j];
            #pragma unroll
            for (int i = 0; i < 4; i++)
                #pragma unroll
                for (int j = 0; j < 8; j++) sacc[i][j] += a[i] * kv[j];
        }
        const bool diag = (kb == qb);
        #pragma unroll
        for (int i = 0; i < 4; i++)
            #pragma unroll
            for (int j = 0; j < 8; j++) {
                int r = r0 + i, c = tx + 8 * j;
                float v = sacc[i][j];
                if (diag && c > r) v = -1e30f;
                Ss[r * 65 + c] = v;
            }
        __syncthreads();

        // online softmax, 1 thread per row
        if (tid < 64) {
            int r = tid;
            float mold = m_s[r];
            float mx = mold;
            for (int c = 0; c < 64; c++) mx = fmaxf(mx, Ss[r * 65 + c]);
            float corr = __expf(mold - mx);
            float sum = 0.f;
            for (int c = 0; c < 64; c++) {
                float p = __expf(Ss[r * 65 + c] - mx);
                Ss[r * 65 + c] = p;
                sum += p;
            }
            m_s[r] = mx;
            l_s[r] = l_s[r] * corr + sum;
            c_s[r] = corr;
        }
        __syncthreads();

        // O = O*corr + P V   (cols d = tx*4 + 32*jj + u)
        float cr[4];
        #pragma unroll
        for (int i = 0; i < 4; i++) cr[i] = c_s[r0 + i];
        #pragma unroll
        for (int i = 0; i < 4; i++)
            #pragma unroll
            for (int n = 0; n < 16; n++) O[i][n] *= cr[i];
        #pragma unroll 2
        for (int c = 0; c < 64; c++) {
            float a[4];
            #pragma unroll
            for (int i = 0; i < 4; i++) a[i] = Ss[(r0 + i) * 65 + c];
            float vv[16];
            #pragma unroll
            for (int jj = 0; jj < 4; jj++)
                *(float4*)&vv[jj * 4] = *(const float4*)&Vs[c * 128 + tx * 4 + 32 * jj];
            #pragma unroll
            for (int i = 0; i < 4; i++)
                #pragma unroll
                for (int n = 0; n < 16; n++) O[i][n] += a[i] * vv[n];
        }
    }

    float li[4];
    #pragma unroll
    for (int i = 0; i < 4; i++) li[i] = 1.f / l_s[r0 + i];
    const size_t obase = ((size_t)b * TT) * CC + h * HD;
    #pragma unroll
    for (int i = 0; i < 4; i++) {
        size_t rowoff = obase + (size_t)(q0 + r0 + i) * CC;
        #pragma unroll
        for (int jj = 0; jj < 4; jj++) {
            float4 v;
            v.x = O[i][jj * 4 + 0] * li[i];
            v.y = O[i][jj * 4 + 1] * li[i];
            v.z = O[i][jj * 4 + 2] * li[i];
            v.w = O[i][jj * 4 + 3] * li[i];
            *(float4*)&out[rowoff + tx * 4 + 32 * jj] = v;
        }
    }
}

// ---------------- host launcher -----------------------------------------------
extern "C" void kernel_launch(void* const* d_in, const int* in_sizes, int n_in,
                              void* d_out, int out_size) {
    const float* x     = (const float*)d_in[0];
    const float* Wq    = (const float*)d_in[1];
    const float* Wk    = (const float*)d_in[2];
    const float* Wv    = (const float*)d_in[3];
    const float* Wp    = (const float*)d_in[4];
    const float* bp    = (const float*)d_in[5];
    const float* W1    = (const float*)d_in[6];
    const float* b1    = (const float*)d_in[7];
    const float* W2    = (const float*)d_in[8];
    const float* b2    = (const float*)d_in[9];
    const float* g1    = (const float*)d_in[10];
    const float* beta1 = (const float*)d_in[11];
    const float* g2    = (const float*)d_in[12];
    const float* beta2 = (const float*)d_in[13];
    float* out = (float*)d_out;

    float *h1, *qkv, *attn, *x1, *h2, *ffn, *wqkv;
    cudaGetSymbolAddress((void**)&h1,   g_h1);
    cudaGetSymbolAddress((void**)&qkv,  g_qkv);
    cudaGetSymbolAddress((void**)&attn, g_attn);
    cudaGetSymbolAddress((void**)&x1,   g_x1);
    cudaGetSymbolAddress((void**)&h2,   g_h2);
    cudaGetSymbolAddress((void**)&ffn,  g_ffn);
    cudaGetSymbolAddress((void**)&wqkv, g_wqkv);

    const int attn_smem = (128 * 65 * 2 + 64 * 128 + 64 * 65 + 192) * 4;  // 116736 B
    cudaFuncSetAttribute(attention_kernel,
                         cudaFuncAttributeMaxDynamicSharedMemorySize, attn_smem);

    // 1. LN1
    ln_kernel<<<NTOK, 256>>>(x, g1, beta1, h1);
    // 2. pack qkv weights
    pack_qkv_kernel<<<(3 * CC * CC + 255) / 256, 256>>>(Wq, Wk, Wv, wqkv);
    // 3. QKV gemm  [8192, 2048] x [2048, 6144]
    gemm_kernel<false, false, false><<<dim3(QKVN / 128, NTOK / 128), 256>>>(
        h1, wqkv, nullptr, nullptr, qkv, NTOK, QKVN, CC);
    // 4. attention
    attention_kernel<<<dim3(TT / 64, BB * HH), 128, attn_smem>>>(qkv, attn);
    // 5. proj: x1 = x + attn @ Wp + bp
    gemm_kernel<true, true, false><<<dim3(CC / 128, NTOK / 128), 256>>>(
        attn, Wp, bp, x, x1, NTOK, CC, CC);
    // 6. LN2
    ln_kernel<<<NTOK, 256>>>(x1, g2, beta2, h2);
    // 7. FFN1: ffn = gelu(h2 @ W1 + b1)
    gemm_kernel<true, false, true><<<dim3(C4 / 128, NTOK / 128), 256>>>(
        h2, W1, b1, nullptr, ffn, NTOK, C4, CC);
    // 8. FFN2: out = x1 + ffn @ W2 + b2
    gemm_kernel<true, true, false><<<dim3(CC / 128, NTOK / 128), 256>>>(
        ffn, W2, b2, x1, out, NTOK, CC, C4);
}

// round 4
// speedup vs baseline: 2.2971x; 2.2971x over previous
#include <cuda_runtime.h>
#include <cuda_bf16.h>
#include <math.h>

// Problem constants
#define BB 4
#define TT 2048
#define CC 2048
#define HH 16
#define HD 128
#define NTOK (BB*TT)          // 8192
#define C4 (4*CC)             // 8192
#define QKVN (3*CC)           // 6144

// ------------------------------------------------------------------
// scratch (device globals; allocation is forbidden)
// ------------------------------------------------------------------
__device__ __nv_bfloat16 g_h1h[(size_t)NTOK * CC];
__device__ __nv_bfloat16 g_h1l[(size_t)NTOK * CC];
__device__ float         g_qkv[(size_t)NTOK * QKVN];
__device__ __nv_bfloat16 g_ath[(size_t)NTOK * CC];
__device__ __nv_bfloat16 g_atl[(size_t)NTOK * CC];
__device__ float         g_x1 [(size_t)NTOK * CC];
__device__ __nv_bfloat16 g_h2h[(size_t)NTOK * CC];
__device__ __nv_bfloat16 g_h2l[(size_t)NTOK * CC];
__device__ __nv_bfloat16 g_fh [(size_t)NTOK * C4];
__device__ __nv_bfloat16 g_fl [(size_t)NTOK * C4];
// weights, transposed to [N][K] bf16 hi/lo
__device__ __nv_bfloat16 g_wqh[(size_t)QKVN * CC];
__device__ __nv_bfloat16 g_wql[(size_t)QKVN * CC];
__device__ __nv_bfloat16 g_wph[(size_t)CC * CC];
__device__ __nv_bfloat16 g_wpl[(size_t)CC * CC];
__device__ __nv_bfloat16 g_w1h[(size_t)C4 * CC];
__device__ __nv_bfloat16 g_w1l[(size_t)C4 * CC];
__device__ __nv_bfloat16 g_w2h[(size_t)CC * C4];
__device__ __nv_bfloat16 g_w2l[(size_t)CC * C4];

// ------------------------------------------------------------------
// helpers (all arch-neutral: sm_80+ features only)
// ------------------------------------------------------------------
__device__ __forceinline__ unsigned smem_u32(const void* p) {
    return (unsigned)__cvta_generic_to_shared(p);
}
__device__ __forceinline__ void cp16(unsigned dst, const void* src) {
    asm volatile("cp.async.cg.shared.global [%0], [%1], 16;" :: "r"(dst), "l"(src));
}
#define CP_COMMIT() asm volatile("cp.async.commit_group;" ::: "memory")
#define CP_WAIT1()  asm volatile("cp.async.wait_group 1;" ::: "memory")
#define CP_WAIT0()  asm volatile("cp.async.wait_group 0;" ::: "memory")

__device__ __forceinline__ void ldm_x4(unsigned* r, unsigned addr) {
    asm volatile("ldmatrix.sync.aligned.m8n8.x4.shared.b16 {%0,%1,%2,%3}, [%4];"
                 : "=r"(r[0]), "=r"(r[1]), "=r"(r[2]), "=r"(r[3]) : "r"(addr));
}
__device__ __forceinline__ void ldm_x2(unsigned* r, unsigned addr) {
    asm volatile("ldmatrix.sync.aligned.m8n8.x2.shared.b16 {%0,%1}, [%2];"
                 : "=r"(r[0]), "=r"(r[1]) : "r"(addr));
}
__device__ __forceinline__ void mma_bf16(float* c, const unsigned* a, const unsigned* b) {
    asm volatile(
        "mma.sync.aligned.m16n8k16.row.col.f32.bf16.bf16.f32 "
        "{%0,%1,%2,%3}, {%4,%5,%6,%7}, {%8,%9}, {%0,%1,%2,%3};"
        : "+f"(c[0]), "+f"(c[1]), "+f"(c[2]), "+f"(c[3])
        : "r"(a[0]), "r"(a[1]), "r"(a[2]), "r"(a[3]), "r"(b[0]), "r"(b[1]));
}

// ------------------------------------------------------------------
// hi/lo split helper
// ------------------------------------------------------------------
__device__ __forceinline__ void split_store(float v, __nv_bfloat16* ph, __nv_bfloat16* pl) {
    __nv_bfloat16 h = __float2bfloat16(v);
    *ph = h;
    *pl = __float2bfloat16(v - __bfloat162float(h));
}
__device__ __forceinline__ float gelu_exact(float v) {
    return 0.5f * v * (1.0f + erff(v * 0.7071067811865475f));
}

// ------------------------------------------------------------------
// layernorm -> bf16 hi/lo
// ------------------------------------------------------------------
__global__ void ln_kernel(const float* __restrict__ x, const float* __restrict__ g,
                          const float* __restrict__ beta,
                          __nv_bfloat16* __restrict__ oh, __nv_bfloat16* __restrict__ ol) {
    int t = blockIdx.x;
    const float* xr = x + (size_t)t * CC;
    float s = 0.f, s2 = 0.f;
    for (int i = threadIdx.x; i < CC; i += 256) { float v = xr[i]; s += v; s2 += v * v; }
    __shared__ float red0[8], red1[8];
    #pragma unroll
    for (int o = 16; o; o >>= 1) {
        s  += __shfl_xor_sync(0xffffffffu, s,  o);
        s2 += __shfl_xor_sync(0xffffffffu, s2, o);
    }
    int w = threadIdx.x >> 5, l = threadIdx.x & 31;
    if (l == 0) { red0[w] = s; red1[w] = s2; }
    __syncthreads();
    if (w == 0) {
        s  = (l < 8) ? red0[l] : 0.f;
        s2 = (l < 8) ? red1[l] : 0.f;
        #pragma unroll
        for (int o = 4; o; o >>= 1) {
            s  += __shfl_xor_sync(0xffffffffu, s,  o);
            s2 += __shfl_xor_sync(0xffffffffu, s2, o);
        }
        if (l == 0) { red0[0] = s; red1[0] = s2; }
    }
    __syncthreads();
    float mean = red0[0] * (1.f / CC);
    float var  = red1[0] * (1.f / CC) - mean * mean;
    float rstd = rsqrtf(var + 1e-5f);
    size_t base = (size_t)t * CC;
    for (int i = threadIdx.x; i < CC; i += 256) {
        float v = (xr[i] - mean) * rstd * g[i] + beta[i];
        split_store(v, &oh[base + i], &ol[base + i]);
    }
}

// ------------------------------------------------------------------
// tiled transpose + bf16 split:  out[c][r] = in[r][c]
// ------------------------------------------------------------------
__global__ void transpose_split_kernel(const float* __restrict__ in,
                                       __nv_bfloat16* __restrict__ oh,
                                       __nv_bfloat16* __restrict__ ol,
                                       int Cn, size_t ibs, int rpb, int out_ld) {
    __shared__ float tile[32][33];
    int tx = threadIdx.x, ty = threadIdx.y;
    int c0 = blockIdx.x * 32, r0 = blockIdx.y * 32, z = blockIdx.z;
    const float* src = in + (size_t)z * ibs;
    #pragma unroll
    for (int i = ty; i < 32; i += 8)
        tile[i][tx] = src[(size_t)(r0 + i) * Cn + c0 + tx];
    __syncthreads();
    #pragma unroll
    for (int i = ty; i < 32; i += 8) {
        float v = tile[tx][i];
        size_t o = ((size_t)z * rpb + c0 + i) * out_ld + r0 + tx;
        split_store(v, &oh[o], &ol[o]);
    }
}

// ------------------------------------------------------------------
// split-bf16 GEMM via mma.sync:  C[M,N] = A[M,K] * B^T  (B stored [N][K])
// CTA tile 128x128, warp tile 64x32, K-chunk 32, cp.async double buffer.
// smem per stage: Ah | Al | Bh | Bl, each 128x32 bf16 = 8KB, swizzled.
// ------------------------------------------------------------------
#define TILE_BYTES  8192u
#define STAGE_BYTES 32768u
#define GEMM_SMEM   65536

__device__ __forceinline__ unsigned sw_off(int row, int chunk) {
    return (unsigned)(row * 64 + ((chunk ^ ((row >> 1) & 3)) << 4));
}

template<bool BIAS, bool RES, bool GELU, bool SPLIT>
__global__ __launch_bounds__(256)
void gemm_mma(const __nv_bfloat16* __restrict__ Ah, const __nv_bfloat16* __restrict__ Al,
              const __nv_bfloat16* __restrict__ Bh, const __nv_bfloat16* __restrict__ Bl,
              const float* __restrict__ bias, const float* __restrict__ res,
              float* __restrict__ outF,
              __nv_bfloat16* __restrict__ outH, __nv_bfloat16* __restrict__ outL,
              int N, int K) {
    extern __shared__ __align__(128) char smem[];
    const int tid  = threadIdx.x;
    const int wid  = tid >> 5, lane = tid & 31;
    const int wm   = wid >> 2, wn = wid & 3;          // warp grid 2x4
    const int m0   = blockIdx.y * 128, n0 = blockIdx.x * 128;
    const unsigned sbase = smem_u32(smem);

    float acc[4][4][4];
    #pragma unroll
    for (int i = 0; i < 4; i++)
        #pragma unroll
        for (int j = 0; j < 4; j++)
            #pragma unroll
            for (int r = 0; r < 4; r++) acc[i][j][r] = 0.f;

    const __nv_bfloat16* bases[4] = {Ah, Al, Bh, Bl};

    auto load_stage = [&](int c, int s) {
        const int k0 = c << 5;
        const unsigned sb = sbase + (unsigned)s * STAGE_BYTES;
        #pragma unroll
        for (int t4 = 0; t4 < 4; t4++) {      // tile index
            #pragma unroll
            for (int h = 0; h < 2; h++) {
                int within = tid + (h << 8);  // 0..511
                int row = within >> 2, ch = within & 3;
                int grow = (t4 < 2 ? m0 : n0) + row;
                const __nv_bfloat16* gp = bases[t4] + (size_t)grow * K + k0 + (ch << 3);
                cp16(sb + (unsigned)t4 * TILE_BYTES + sw_off(row, ch), gp);
            }
        }
    };

    const int nch = K >> 5;
    load_stage(0, 0);
    CP_COMMIT();

    for (int c = 0; c < nch; c++) {
        if (c + 1 < nch) {
            load_stage(c + 1, (c + 1) & 1);
            CP_COMMIT();
            CP_WAIT1();
        } else {
            CP_WAIT0();
        }
        __syncthreads();

        const unsigned sb = sbase + (unsigned)(c & 1) * STAGE_BYTES;
        const int lrow = (lane & 7) + ((lane >> 3) & 1) * 8;
        const int lch  = lane >> 4;
        const int bl16 = lane & 15;
        const int brow = bl16 & 7, bch = bl16 >> 3;

        #pragma unroll
        for (int ks = 0; ks < 2; ks++) {
            unsigned afh[4][4], afl[4][4], bfh[4][2], bfl[4][2];
            #pragma unroll
            for (int i = 0; i < 4; i++) {
                unsigned a_addr = sb + sw_off(wm * 64 + i * 16 + lrow, 2 * ks + lch);
                ldm_x4(afh[i], a_addr);
                ldm_x4(afl[i], a_addr + TILE_BYTES);
            }
            #pragma unroll
            for (int j = 0; j < 4; j++) {
                unsigned b_addr = sb + 2 * TILE_BYTES +
                                  sw_off(wn * 32 + j * 8 + brow, 2 * ks + bch);
                ldm_x2(bfh[j], b_addr);
                ldm_x2(bfl[j], b_addr + TILE_BYTES);
            }
            #pragma unroll
            for (int i = 0; i < 4; i++)
                #pragma unroll
                for (int j = 0; j < 4; j++) {
                    mma_bf16(acc[i][j], afh[i], bfh[j]);
                    mma_bf16(acc[i][j], afh[i], bfl[j]);
                    mma_bf16(acc[i][j], afl[i], bfh[j]);
                }
        }
        __syncthreads();
    }

    // epilogue straight from registers
    #pragma unroll
    for (int i = 0; i < 4; i++) {
        #pragma unroll
        for (int j = 0; j < 4; j++) {
            int row0 = m0 + wm * 64 + i * 16 + (lane >> 2);
            int col  = n0 + wn * 32 + j * 8 + (lane & 3) * 2;
            #pragma unroll
            for (int hrow = 0; hrow < 2; hrow++) {
                int row = row0 + hrow * 8;
                float xv = acc[i][j][hrow * 2 + 0];
                float yv = acc[i][j][hrow * 2 + 1];
                if (BIAS) { xv += bias[col]; yv += bias[col + 1]; }
                if (GELU) { xv = gelu_exact(xv); yv = gelu_exact(yv); }
                size_t off = (size_t)row * N + col;
                if (RES) {
                    float2 rr = *(const float2*)&res[off];
                    xv += rr.x; yv += rr.y;
                }
                if (SPLIT) {
                    split_store(xv, &outH[off], &outL[off]);
                    split_store(yv, &outH[off + 1], &outL[off + 1]);
                } else {
                    float2 o; o.x = xv; o.y = yv;
                    *(float2*)&outF[off] = o;
                }
            }
        }
    }
}

// ------------------------------------------------------------------
// causal flash attention (fp32) -> bf16 hi/lo output (via device globals)
// ------------------------------------------------------------------
__global__ __launch_bounds__(128)
void attention_kernel(const float* __restrict__ qkv) {
    extern __shared__ float sm[];
    float* Qt  = sm;               // [128][65]
    float* Kt  = Qt + 128 * 65;    // [128][65]
    float* Vs  = Kt + 128 * 65;    // [64][128]
    float* Ss  = Vs + 64 * 128;    // [64][65]
    float* m_s = Ss + 64 * 65;
    float* l_s = m_s + 64;
    float* c_s = l_s + 64;

    const int tid = threadIdx.x;
    const int bh = blockIdx.y;
    const int b  = bh >> 4, h = bh & 15;
    const int qb = blockIdx.x;
    const int q0 = qb * 64;
    const float scale = 0.08838834764831845f;

    const size_t base = ((size_t)b * TT) * QKVN + h * HD;

    for (int idx = tid; idx < 64 * 128; idx += 128) {
        int r = idx >> 7, d = idx & 127;
        Qt[d * 65 + r] = qkv[base + (size_t)(q0 + r) * QKVN + d] * scale;
    }
    if (tid < 64) { m_s[tid] = -1e30f; l_s[tid] = 0.f; }

    float O[4][16];
    #pragma unroll
    for (int i = 0; i < 4; i++)
        #pragma unroll
        for (int n = 0; n < 16; n++) O[i][n] = 0.f;

    const int ty = tid >> 3, tx = tid & 7;
    const int r0 = ty * 4;

    for (int kb = 0; kb <= qb; kb++) {
        const int k0 = kb * 64;
        __syncthreads();
        for (int idx = tid; idx < 64 * 128; idx += 128) {
            int cc = idx >> 7, d = idx & 127;
            size_t tk = base + (size_t)(k0 + cc) * QKVN;
            Kt[d * 65 + cc]  = qkv[tk + CC + d];
            Vs[cc * 128 + d] = qkv[tk + 2 * CC + d];
        }
        __syncthreads();

        float sacc[4][8];
        #pragma unroll
        for (int i = 0; i < 4; i++)
            #pragma unroll
            for (int j = 0; j < 8; j++) sacc[i][j] = 0.f;
        #pragma unroll 4
        for (int d = 0; d < 128; d++) {
            float a[4], kv[8];
            #pragma unroll
            for (int i = 0; i < 4; i++) a[i] = Qt[d * 65 + r0 + i];
            #pragma unroll
            for (int j = 0; j < 8; j++) kv[j] = Kt[d * 65 + tx + 8 * j];
            #pragma unroll
            for (int i = 0; i < 4; i++)
                #pragma unroll
                for (int j = 0; j < 8; j++) sacc[i][j] += a[i] * kv[j];
        }
        const bool diag = (kb == qb);
        #pragma unroll
        for (int i = 0; i < 4; i++)
            #pragma unroll
            for (int j = 0; j < 8; j++) {
                int r = r0 + i, cc = tx + 8 * j;
                float v = sacc[i][j];
                if (diag && cc > r) v = -1e30f;
                Ss[r * 65 + cc] = v;
            }
        __syncthreads();

        if (tid < 64) {
            int r = tid;
            float mold = m_s[r];
            float mx = mold;
            for (int cc = 0; cc < 64; cc++) mx = fmaxf(mx, Ss[r * 65 + cc]);
            float corr = __expf(mold - mx);
            float sum = 0.f;
            for (int cc = 0; cc < 64; cc++) {
                float p = __expf(Ss[r * 65 + cc] - mx);
                Ss[r * 65 + cc] = p;
                sum += p;
            }
            m_s[r] = mx;
            l_s[r] = l_s[r] * corr + sum;
            c_s[r] = corr;
        }
        __syncthreads();

        float cr[4];
        #pragma unroll
        for (int i = 0; i < 4; i++) cr[i] = c_s[r0 + i];
        #pragma unroll
        for (int i = 0; i < 4; i++)
            #pragma unroll
            for (int n = 0; n < 16; n++) O[i][n] *= cr[i];
        #pragma unroll 2
        for (int cc = 0; cc < 64; cc++) {
            float a[4];
            #pragma unroll
            for (int i = 0; i < 4; i++) a[i] = Ss[(r0 + i) * 65 + cc];
            float vv[16];
            #pragma unroll
            for (int jj = 0; jj < 4; jj++)
                *(float4*)&vv[jj * 4] = *(const float4*)&Vs[cc * 128 + tx * 4 + 32 * jj];
            #pragma unroll
            for (int i = 0; i < 4; i++)
                #pragma unroll
                for (int n = 0; n < 16; n++) O[i][n] += a[i] * vv[n];
        }
    }

    float li[4];
    #pragma unroll
    for (int i = 0; i < 4; i++) li[i] = 1.f / l_s[r0 + i];
    const size_t obase = ((size_t)b * TT) * CC + h * HD;
    #pragma unroll
    for (int i = 0; i < 4; i++) {
        size_t rowoff = obase + (size_t)(q0 + r0 + i) * CC;
        #pragma unroll
        for (int jj = 0; jj < 4; jj++) {
            #pragma unroll
            for (int u = 0; u < 4; u++) {
                float v = O[i][jj * 4 + u] * li[i];
                size_t o = rowoff + tx * 4 + 32 * jj + u;
                split_store(v, &g_ath[o], &g_atl[o]);
            }
        }
    }
}

// ------------------------------------------------------------------
// host launcher
// ------------------------------------------------------------------
extern "C" void kernel_launch(void* const* d_in, const int* in_sizes, int n_in,
                              void* d_out, int out_size) {
    const float* x     = (const float*)d_in[0];
    const float* Wq    = (const float*)d_in[1];
    const float* Wk    = (const float*)d_in[2];
    const float* Wv    = (const float*)d_in[3];
    const float* Wp    = (const float*)d_in[4];
    const float* bp    = (const float*)d_in[5];
    const float* W1    = (const float*)d_in[6];
    const float* b1    = (const float*)d_in[7];
    const float* W2    = (const float*)d_in[8];
    const float* b2    = (const float*)d_in[9];
    const float* g1    = (const float*)d_in[10];
    const float* beta1 = (const float*)d_in[11];
    const float* g2    = (const float*)d_in[12];
    const float* beta2 = (const float*)d_in[13];
    float* out = (float*)d_out;

    __nv_bfloat16 *h1h, *h1l, *ath, *atl, *h2h, *h2l, *fh, *fl;
    __nv_bfloat16 *wqh, *wql, *wph, *wpl, *w1h, *w1l, *w2h, *w2l;
    float *qkv, *x1;
    cudaGetSymbolAddress((void**)&h1h, g_h1h);  cudaGetSymbolAddress((void**)&h1l, g_h1l);
    cudaGetSymbolAddress((void**)&qkv, g_qkv);
    cudaGetSymbolAddress((void**)&ath, g_ath);  cudaGetSymbolAddress((void**)&atl, g_atl);
    cudaGetSymbolAddress((void**)&x1,  g_x1);
    cudaGetSymbolAddress((void**)&h2h, g_h2h);  cudaGetSymbolAddress((void**)&h2l, g_h2l);
    cudaGetSymbolAddress((void**)&fh,  g_fh);   cudaGetSymbolAddress((void**)&fl,  g_fl);
    cudaGetSymbolAddress((void**)&wqh, g_wqh);  cudaGetSymbolAddress((void**)&wql, g_wql);
    cudaGetSymbolAddress((void**)&wph, g_wph);  cudaGetSymbolAddress((void**)&wpl, g_wpl);
    cudaGetSymbolAddress((void**)&w1h, g_w1h);  cudaGetSymbolAddress((void**)&w1l, g_w1l);
    cudaGetSymbolAddress((void**)&w2h, g_w2h);  cudaGetSymbolAddress((void**)&w2l, g_w2l);

    const int attn_smem = (128 * 65 * 2 + 64 * 128 + 64 * 65 + 192) * 4;
    cudaFuncSetAttribute(attention_kernel,
                         cudaFuncAttributeMaxDynamicSharedMemorySize, attn_smem);
    cudaFuncSetAttribute(gemm_mma<false, false, false, false>,
                         cudaFuncAttributeMaxDynamicSharedMemorySize, GEMM_SMEM);
    cudaFuncSetAttribute(gemm_mma<true, true, false, false>,
                         cudaFuncAttributeMaxDynamicSharedMemorySize, GEMM_SMEM);
    cudaFuncSetAttribute(gemm_mma<true, false, true, true>,
                         cudaFuncAttributeMaxDynamicSharedMemorySize, GEMM_SMEM);

    dim3 tb(32, 8);
    // weight prep: transpose + hi/lo split
    for (int s = 0; s < 3; s++) {
        const float* Ws = (s == 0) ? Wq : (s == 1) ? Wk : Wv;
        transpose_split_kernel<<<dim3(HD / 32, CC / 32, HH), tb>>>(
            Ws, wqh + (size_t)s * CC * CC, wql + (size_t)s * CC * CC,
            HD, (size_t)CC * HD, HD, CC);
    }
    transpose_split_kernel<<<dim3(CC / 32, CC / 32, 1), tb>>>(Wp, wph, wpl, CC, 0, CC, CC);
    transpose_split_kernel<<<dim3(C4 / 32, CC / 32, 1), tb>>>(W1, w1h, w1l, C4, 0, C4, CC);
    transpose_split_kernel<<<dim3(CC / 32, C4 / 32, 1), tb>>>(W2, w2h, w2l, CC, 0, CC, C4);

    // 1. LN1 -> h1 (bf16 hi/lo)
    ln_kernel<<<NTOK, 256>>>(x, g1, beta1, h1h, h1l);
    // 2. QKV GEMM: qkv = h1 @ Wqkv   [8192, 6144], fp32 out
    gemm_mma<false, false, false, false><<<dim3(QKVN / 128, NTOK / 128), 256, GEMM_SMEM>>>(
        h1h, h1l, wqh, wql, nullptr, nullptr, qkv, nullptr, nullptr, QKVN, CC);
    // 3. attention -> attn (bf16 hi/lo, written to device globals)
    attention_kernel<<<dim3(TT / 64, BB * HH), 128, attn_smem>>>(qkv);
    // 4. proj: x1 = x + attn @ Wp + bp   (fp32)
    gemm_mma<true, true, false, false><<<dim3(CC / 128, NTOK / 128), 256, GEMM_SMEM>>>(
        ath, atl, wph, wpl, bp, x, x1, nullptr, nullptr, CC, CC);
    // 5. LN2 -> h2
    ln_kernel<<<NTOK, 256>>>(x1, g2, beta2, h2h, h2l);
    // 6. FFN1: f = gelu(h2 @ W1 + b1) -> bf16 hi/lo
    gemm_mma<true, false, true, true><<<dim3(C4 / 128, NTOK / 128), 256, GEMM_SMEM>>>(
        h2h, h2l, w1h, w1l, b1, nullptr, nullptr, fh, fl, C4, CC);
    // 7. FFN2: out = x1 + f @ W2 + b2   (fp32)
    gemm_mma<true, true, false, false><<<dim3(CC / 128, NTOK / 128), 256, GEMM_SMEM>>>(
        fh, fl, w2h, w2l, b2, x1, out, nullptr, nullptr, CC, C4);
}

// round 5
// speedup vs baseline: 3.3891x; 1.4754x over previous
#include <cuda_runtime.h>
#include <cuda_bf16.h>
#include <math.h>

// Problem constants
#define BB 4
#define TT 2048
#define CC 2048
#define HH 16
#define HD 128
#define NTOK (BB*TT)          // 8192
#define C4 (4*CC)             // 8192
#define QKVN (3*CC)           // 6144

// ------------------------------------------------------------------
// scratch (device globals; allocation is forbidden)
// ------------------------------------------------------------------
__device__ __nv_bfloat16 g_h1h[(size_t)NTOK * CC];
__device__ __nv_bfloat16 g_h1l[(size_t)NTOK * CC];
__device__ __nv_bfloat16 g_qkvh[(size_t)NTOK * QKVN];
__device__ __nv_bfloat16 g_qkvl[(size_t)NTOK * QKVN];
__device__ __nv_bfloat16 g_ath[(size_t)NTOK * CC];
__device__ __nv_bfloat16 g_atl[(size_t)NTOK * CC];
__device__ float         g_x1 [(size_t)NTOK * CC];
__device__ __nv_bfloat16 g_h2h[(size_t)NTOK * CC];
__device__ __nv_bfloat16 g_h2l[(size_t)NTOK * CC];
__device__ __nv_bfloat16 g_fh [(size_t)NTOK * C4];
__device__ __nv_bfloat16 g_fl [(size_t)NTOK * C4];
// weights, transposed to [N][K] bf16 hi/lo
__device__ __nv_bfloat16 g_wqh[(size_t)QKVN * CC];
__device__ __nv_bfloat16 g_wql[(size_t)QKVN * CC];
__device__ __nv_bfloat16 g_wph[(size_t)CC * CC];
__device__ __nv_bfloat16 g_wpl[(size_t)CC * CC];
__device__ __nv_bfloat16 g_w1h[(size_t)C4 * CC];
__device__ __nv_bfloat16 g_w1l[(size_t)C4 * CC];
__device__ __nv_bfloat16 g_w2h[(size_t)CC * C4];
__device__ __nv_bfloat16 g_w2l[(size_t)CC * C4];

// ------------------------------------------------------------------
// helpers (arch-neutral, sm_80+)
// ------------------------------------------------------------------
__device__ __forceinline__ unsigned smem_u32(const void* p) {
    return (unsigned)__cvta_generic_to_shared(p);
}
__device__ __forceinline__ void cp16(unsigned dst, const void* src) {
    asm volatile("cp.async.cg.shared.global [%0], [%1], 16;" :: "r"(dst), "l"(src));
}
#define CP_COMMIT() asm volatile("cp.async.commit_group;" ::: "memory")
#define CP_WAIT1()  asm volatile("cp.async.wait_group 1;" ::: "memory")
#define CP_WAIT0()  asm volatile("cp.async.wait_group 0;" ::: "memory")

__device__ __forceinline__ void ldm_x4(unsigned* r, unsigned addr) {
    asm volatile("ldmatrix.sync.aligned.m8n8.x4.shared.b16 {%0,%1,%2,%3}, [%4];"
                 : "=r"(r[0]), "=r"(r[1]), "=r"(r[2]), "=r"(r[3]) : "r"(addr));
}
__device__ __forceinline__ void ldm_x4t(unsigned* r, unsigned addr) {
    asm volatile("ldmatrix.sync.aligned.m8n8.x4.trans.shared.b16 {%0,%1,%2,%3}, [%4];"
                 : "=r"(r[0]), "=r"(r[1]), "=r"(r[2]), "=r"(r[3]) : "r"(addr));
}
__device__ __forceinline__ void ldm_x2(unsigned* r, unsigned addr) {
    asm volatile("ldmatrix.sync.aligned.m8n8.x2.shared.b16 {%0,%1}, [%2];"
                 : "=r"(r[0]), "=r"(r[1]) : "r"(addr));
}
__device__ __forceinline__ void mma_bf16(float* c, const unsigned* a, const unsigned* b) {
    asm volatile(
        "mma.sync.aligned.m16n8k16.row.col.f32.bf16.bf16.f32 "
        "{%0,%1,%2,%3}, {%4,%5,%6,%7}, {%8,%9}, {%0,%1,%2,%3};"
        : "+f"(c[0]), "+f"(c[1]), "+f"(c[2]), "+f"(c[3])
        : "r"(a[0]), "r"(a[1]), "r"(a[2]), "r"(a[3]), "r"(b[0]), "r"(b[1]));
}

__device__ __forceinline__ void split_store(float v, __nv_bfloat16* ph, __nv_bfloat16* pl) {
    __nv_bfloat16 h = __float2bfloat16(v);
    *ph = h;
    *pl = __float2bfloat16(v - __bfloat162float(h));
}
__device__ __forceinline__ unsigned pack2(__nv_bfloat16 a, __nv_bfloat16 b) {
    __nv_bfloat162 t; t.x = a; t.y = b;
    return *(unsigned*)&t;
}
__device__ __forceinline__ float gelu_exact(float v) {
    return 0.5f * v * (1.0f + erff(v * 0.7071067811865475f));
}

// ------------------------------------------------------------------
// layernorm -> bf16 hi/lo
// ------------------------------------------------------------------
__global__ void ln_kernel(const float* __restrict__ x, const float* __restrict__ g,
                          const float* __restrict__ beta,
                          __nv_bfloat16* __restrict__ oh, __nv_bfloat16* __restrict__ ol) {
    int t = blockIdx.x;
    const float* xr = x + (size_t)t * CC;
    float s = 0.f, s2 = 0.f;
    for (int i = threadIdx.x; i < CC; i += 256) { float v = xr[i]; s += v; s2 += v * v; }
    __shared__ float red0[8], red1[8];
    #pragma unroll
    for (int o = 16; o; o >>= 1) {
        s  += __shfl_xor_sync(0xffffffffu, s,  o);
        s2 += __shfl_xor_sync(0xffffffffu, s2, o);
    }
    int w = threadIdx.x >> 5, l = threadIdx.x & 31;
    if (l == 0) { red0[w] = s; red1[w] = s2; }
    __syncthreads();
    if (w == 0) {
        s  = (l < 8) ? red0[l] : 0.f;
        s2 = (l < 8) ? red1[l] : 0.f;
        #pragma unroll
        for (int o = 4; o; o >>= 1) {
            s  += __shfl_xor_sync(0xffffffffu, s,  o);
            s2 += __shfl_xor_sync(0xffffffffu, s2, o);
        }
        if (l == 0) { red0[0] = s; red1[0] = s2; }
    }
    __syncthreads();
    float mean = red0[0] * (1.f / CC);
    float var  = red1[0] * (1.f / CC) - mean * mean;
    float rstd = rsqrtf(var + 1e-5f);
    size_t base = (size_t)t * CC;
    for (int i = threadIdx.x; i < CC; i += 256) {
        float v = (xr[i] - mean) * rstd * g[i] + beta[i];
        split_store(v, &oh[base + i], &ol[base + i]);
    }
}

// ------------------------------------------------------------------
// tiled transpose + bf16 split:  out[c][r] = in[r][c]
// ------------------------------------------------------------------
__global__ void transpose_split_kernel(const float* __restrict__ in,
                                       __nv_bfloat16* __restrict__ oh,
                                       __nv_bfloat16* __restrict__ ol,
                                       int Cn, size_t ibs, int rpb, int out_ld) {
    __shared__ float tile[32][33];
    int tx = threadIdx.x, ty = threadIdx.y;
    int c0 = blockIdx.x * 32, r0 = blockIdx.y * 32, z = blockIdx.z;
    const float* src = in + (size_t)z * ibs;
    #pragma unroll
    for (int i = ty; i < 32; i += 8)
        tile[i][tx] = src[(size_t)(r0 + i) * Cn + c0 + tx];
    __syncthreads();
    #pragma unroll
    for (int i = ty; i < 32; i += 8) {
        float v = tile[tx][i];
        size_t o = ((size_t)z * rpb + c0 + i) * out_ld + r0 + tx;
        split_store(v, &oh[o], &ol[o]);
    }
}

// ------------------------------------------------------------------
// split-bf16 GEMM via mma.sync:  C[M,N] = A[M,K] * B^T  (B stored [N][K])
// ------------------------------------------------------------------
#define TILE_BYTES  8192u
#define STAGE_BYTES 32768u
#define GEMM_SMEM   65536

__device__ __forceinline__ unsigned sw_off(int row, int chunk) {
    return (unsigned)(row * 64 + ((chunk ^ ((row >> 1) & 3)) << 4));
}

template<bool BIAS, bool RES, bool GELU, bool SPLIT>
__global__ __launch_bounds__(256)
void gemm_mma(const __nv_bfloat16* __restrict__ Ah, const __nv_bfloat16* __restrict__ Al,
              const __nv_bfloat16* __restrict__ Bh, const __nv_bfloat16* __restrict__ Bl,
              const float* __restrict__ bias, const float* __restrict__ res,
              float* __restrict__ outF,
              __nv_bfloat16* __restrict__ outH, __nv_bfloat16* __restrict__ outL,
              int N, int K) {
    extern __shared__ __align__(128) char smem[];
    const int tid  = threadIdx.x;
    const int wid  = tid >> 5, lane = tid & 31;
    const int wm   = wid >> 2, wn = wid & 3;
    const int m0   = blockIdx.y * 128, n0 = blockIdx.x * 128;
    const unsigned sbase = smem_u32(smem);

    float acc[4][4][4];
    #pragma unroll
    for (int i = 0; i < 4; i++)
        #pragma unroll
        for (int j = 0; j < 4; j++)
            #pragma unroll
            for (int r = 0; r < 4; r++) acc[i][j][r] = 0.f;

    const __nv_bfloat16* bases[4] = {Ah, Al, Bh, Bl};

    auto load_stage = [&](int c, int s) {
        const int k0 = c << 5;
        const unsigned sb = sbase + (unsigned)s * STAGE_BYTES;
        #pragma unroll
        for (int t4 = 0; t4 < 4; t4++) {
            #pragma unroll
            for (int h = 0; h < 2; h++) {
                int within = tid + (h << 8);
                int row = within >> 2, ch = within & 3;
                int grow = (t4 < 2 ? m0 : n0) + row;
                const __nv_bfloat16* gp = bases[t4] + (size_t)grow * K + k0 + (ch << 3);
                cp16(sb + (unsigned)t4 * TILE_BYTES + sw_off(row, ch), gp);
            }
        }
    };

    const int nch = K >> 5;
    load_stage(0, 0);
    CP_COMMIT();

    for (int c = 0; c < nch; c++) {
        if (c + 1 < nch) {
            load_stage(c + 1, (c + 1) & 1);
            CP_COMMIT();
            CP_WAIT1();
        } else {
            CP_WAIT0();
        }
        __syncthreads();

        const unsigned sb = sbase + (unsigned)(c & 1) * STAGE_BYTES;
        const int lrow = (lane & 7) + ((lane >> 3) & 1) * 8;
        const int lch  = lane >> 4;
        const int bl16 = lane & 15;
        const int brow = bl16 & 7, bch = bl16 >> 3;

        #pragma unroll
        for (int ks = 0; ks < 2; ks++) {
            unsigned afh[4][4], afl[4][4], bfh[4][2], bfl[4][2];
            #pragma unroll
            for (int i = 0; i < 4; i++) {
                unsigned a_addr = sb + sw_off(wm * 64 + i * 16 + lrow, 2 * ks + lch);
                ldm_x4(afh[i], a_addr);
                ldm_x4(afl[i], a_addr + TILE_BYTES);
            }
            #pragma unroll
            for (int j = 0; j < 4; j++) {
                unsigned b_addr = sb + 2 * TILE_BYTES +
                                  sw_off(wn * 32 + j * 8 + brow, 2 * ks + bch);
                ldm_x2(bfh[j], b_addr);
                ldm_x2(bfl[j], b_addr + TILE_BYTES);
            }
            #pragma unroll
            for (int i = 0; i < 4; i++)
                #pragma unroll
                for (int j = 0; j < 4; j++) {
                    mma_bf16(acc[i][j], afh[i], bfh[j]);
                    mma_bf16(acc[i][j], afh[i], bfl[j]);
                    mma_bf16(acc[i][j], afl[i], bfh[j]);
                }
        }
        __syncthreads();
    }

    #pragma unroll
    for (int i = 0; i < 4; i++) {
        #pragma unroll
        for (int j = 0; j < 4; j++) {
            int row0 = m0 + wm * 64 + i * 16 + (lane >> 2);
            int col  = n0 + wn * 32 + j * 8 + (lane & 3) * 2;
            #pragma unroll
            for (int hrow = 0; hrow < 2; hrow++) {
                int row = row0 + hrow * 8;
                float xv = acc[i][j][hrow * 2 + 0];
                float yv = acc[i][j][hrow * 2 + 1];
                if (BIAS) { xv += bias[col]; yv += bias[col + 1]; }
                if (GELU) { xv = gelu_exact(xv); yv = gelu_exact(yv); }
                size_t off = (size_t)row * N + col;
                if (RES) {
                    float2 rr = *(const float2*)&res[off];
                    xv += rr.x; yv += rr.y;
                }
                if (SPLIT) {
                    split_store(xv, &outH[off], &outL[off]);
                    split_store(yv, &outH[off + 1], &outL[off + 1]);
                } else {
                    float2 o; o.x = xv; o.y = yv;
                    *(float2*)&outF[off] = o;
                }
            }
        }
    }
}

// ------------------------------------------------------------------
// tensor-core causal flash attention, split-bf16 (3-product) math.
// CTA: one (b,h), 128 queries, 256 threads (8 warps x 16 rows),
// key blocks of 64. smem: Qh|Ql (64K) Kh|Kl (32K) Vh|Vl (32K) = 128K.
// ------------------------------------------------------------------
#define ATTN_SMEM 131072
#define AQH 0u
#define AQL 32768u
#define AKH 65536u
#define AKL 81920u
#define AVH 98304u
#define AVL 114688u

__device__ __forceinline__ unsigned swz256(int row, int c16) {
    return (unsigned)(row * 256 + ((c16 ^ (row & 7)) << 4));
}

__global__ __launch_bounds__(256)
void attention_mma(const __nv_bfloat16* __restrict__ qvh,
                   const __nv_bfloat16* __restrict__ qvl,
                   __nv_bfloat16* __restrict__ oh_g,
                   __nv_bfloat16* __restrict__ ol_g) {
    extern __shared__ __align__(1024) char smem[];
    const unsigned sbase = smem_u32(smem);
    const int tid = threadIdx.x, wid = tid >> 5, lane = tid & 31;
    const int bh = blockIdx.y, b = bh >> 4, h = bh & 15;
    const int qt = ((int)gridDim.x - 1) - (int)blockIdx.x;   // heavy tiles first
    const int q0 = qt * 128;
    const int nkb = 2 * qt + 2;
    const float scale = 0.08838834764831845f;   // 1/sqrt(128)

    const size_t rowbase = (size_t)b * TT;

    // Q fill (once): 2048 cp16 per precision
    #pragma unroll
    for (int i = 0; i < 8; i++) {
        int idx = tid + (i << 8);
        int r = idx >> 4, c16 = idx & 15;
        size_t src = (rowbase + q0 + r) * QKVN + h * HD + c16 * 8;
        unsigned dst = sbase + swz256(r, c16);
        cp16(dst + AQH, qvh + src);
        cp16(dst + AQL, qvl + src);
    }
    CP_COMMIT();

    float oacc[16][4];
    #pragma unroll
    for (int j = 0; j < 16; j++)
        #pragma unroll
        for (int e = 0; e < 4; e++) oacc[j][e] = 0.f;

    float m0 = -1e30f, m1 = -1e30f, sl0 = 0.f, sl1 = 0.f;
    const int wrow = wid * 16;
    const int lrow = (lane & 7) + ((lane >> 3) & 1) * 8;
    const int lch  = lane >> 4;

    for (int kb = 0; kb < nkb; kb++) {
        const int k0 = kb * 64;
        __syncthreads();
        #pragma unroll
        for (int i = 0; i < 4; i++) {
            int idx = tid + (i << 8);
            int r = idx >> 4, c16 = idx & 15;
            size_t srcK = (rowbase + k0 + r) * QKVN + CC + h * HD + c16 * 8;
            size_t srcV = (rowbase + k0 + r) * QKVN + 2 * CC + h * HD + c16 * 8;
            unsigned sw = swz256(r, c16);
            cp16(sbase + AKH + sw, qvh + srcK);
            cp16(sbase + AKL + sw, qvl + srcK);
            cp16(sbase + AVH + sw, qvh + srcV);
            cp16(sbase + AVL + sw, qvl + srcV);
        }
        CP_COMMIT(); CP_WAIT0();
        __syncthreads();

        // ---- S = Q K^T (raw, scale applied at softmax) ----
        float sacc[8][4];
        #pragma unroll
        for (int j = 0; j < 8; j++)
            #pragma unroll
            for (int e = 0; e < 4; e++) sacc[j][e] = 0.f;

        #pragma unroll
        for (int kt = 0; kt < 8; kt++) {
            unsigned qfh[4], qfl[4];
            unsigned qa = sbase + swz256(wrow + lrow, 2 * kt + lch);
            ldm_x4(qfh, qa + AQH);
            ldm_x4(qfl, qa + AQL);
            #pragma unroll
            for (int jp = 0; jp < 4; jp++) {
                unsigned ka = sbase + swz256(jp * 16 + lrow, 2 * kt + lch);
                unsigned rh[4], rl[4];
                ldm_x4(rh, ka + AKH);
                ldm_x4(rl, ka + AKL);
                unsigned b0h[2] = {rh[0], rh[2]}, b1h[2] = {rh[1], rh[3]};
                unsigned b0l[2] = {rl[0], rl[2]}, b1l[2] = {rl[1], rl[3]};
                mma_bf16(sacc[2 * jp],     qfh, b0h);
                mma_bf16(sacc[2 * jp],     qfh, b0l);
                mma_bf16(sacc[2 * jp],     qfl, b0h);
                mma_bf16(sacc[2 * jp + 1], qfh, b1h);
                mma_bf16(sacc[2 * jp + 1], qfh, b1l);
                mma_bf16(sacc[2 * jp + 1], qfl, b1h);
            }
        }

        // ---- causal mask ----
        if (k0 + 63 > q0 + wrow) {
            int qr = q0 + wrow + (lane >> 2);
            int kc = k0 + (lane & 3) * 2;
            #pragma unroll
            for (int j = 0; j < 8; j++) {
                int kk = kc + 8 * j;
                if (kk     > qr)     sacc[j][0] = -1e30f;
                if (kk + 1 > qr)     sacc[j][1] = -1e30f;
                if (kk     > qr + 8) sacc[j][2] = -1e30f;
                if (kk + 1 > qr + 8) sacc[j][3] = -1e30f;
            }
        }

        // ---- online softmax (register-only, quad shuffles) ----
        float mx0 = -1e30f, mx1 = -1e30f;
        #pragma unroll
        for (int j = 0; j < 8; j++) {
            mx0 = fmaxf(mx0, fmaxf(sacc[j][0], sacc[j][1]));
            mx1 = fmaxf(mx1, fmaxf(sacc[j][2], sacc[j][3]));
        }
        mx0 = fmaxf(mx0, __shfl_xor_sync(0xffffffffu, mx0, 1));
        mx0 = fmaxf(mx0, __shfl_xor_sync(0xffffffffu, mx0, 2));
        mx1 = fmaxf(mx1, __shfl_xor_sync(0xffffffffu, mx1, 1));
        mx1 = fmaxf(mx1, __shfl_xor_sync(0xffffffffu, mx1, 2));
        mx0 *= scale; mx1 *= scale;
        float mn0 = fmaxf(m0, mx0), mn1 = fmaxf(m1, mx1);
        float cr0 = __expf(m0 - mn0), cr1 = __expf(m1 - mn1);

        unsigned phr0[8], phr1[8], plr0[8], plr1[8];
        float sum0 = 0.f, sum1 = 0.f;
        #pragma unroll
        for (int j = 0; j < 8; j++) {
            float p0 = __expf(sacc[j][0] * scale - mn0);
            float p1 = __expf(sacc[j][1] * scale - mn0);
            float p2 = __expf(sacc[j][2] * scale - mn1);
            float p3 = __expf(sacc[j][3] * scale - mn1);
            sum0 += p0 + p1; sum1 += p2 + p3;
            __nv_bfloat16 h0 = __float2bfloat16(p0), h1 = __float2bfloat16(p1);
            __nv_bfloat16 h2 = __float2bfloat16(p2), h3 = __float2bfloat16(p3);
            phr0[j] = pack2(h0, h1);
            phr1[j] = pack2(h2, h3);
            plr0[j] = pack2(__float2bfloat16(p0 - __bfloat162float(h0)),
                            __float2bfloat16(p1 - __bfloat162float(h1)));
            plr1[j] = pack2(__float2bfloat16(p2 - __bfloat162float(h2)),
                            __float2bfloat16(p3 - __bfloat162float(h3)));
        }
        sum0 += __shfl_xor_sync(0xffffffffu, sum0, 1);
        sum0 += __shfl_xor_sync(0xffffffffu, sum0, 2);
        sum1 += __shfl_xor_sync(0xffffffffu, sum1, 1);
        sum1 += __shfl_xor_sync(0xffffffffu, sum1, 2);
        sl0 = sl0 * cr0 + sum0;
        sl1 = sl1 * cr1 + sum1;
        m0 = mn0; m1 = mn1;

        #pragma unroll
        for (int j = 0; j < 16; j++) {
            oacc[j][0] *= cr0; oacc[j][1] *= cr0;
            oacc[j][2] *= cr1; oacc[j][3] *= cr1;
        }

        // ---- O += P V  (P frags reused from S acc; V via ldmatrix.trans) ----
        #pragma unroll
        for (int kc = 0; kc < 4; kc++) {
            unsigned pah[4] = {phr0[2 * kc], phr1[2 * kc], phr0[2 * kc + 1], phr1[2 * kc + 1]};
            unsigned pal[4] = {plr0[2 * kc], plr1[2 * kc], plr0[2 * kc + 1], plr1[2 * kc + 1]};
            #pragma unroll
            for (int jp = 0; jp < 8; jp++) {
                unsigned va = sbase + swz256(kc * 16 + lrow, 2 * jp + lch);
                unsigned rh[4], rl[4];
                ldm_x4t(rh, va + AVH);
                ldm_x4t(rl, va + AVL);
                unsigned b0h[2] = {rh[0], rh[1]}, b1h[2] = {rh[2], rh[3]};
                unsigned b0l[2] = {rl[0], rl[1]}, b1l[2] = {rl[2], rl[3]};
                mma_bf16(oacc[2 * jp],     pah, b0h);
                mma_bf16(oacc[2 * jp],     pah, b0l);
                mma_bf16(oacc[2 * jp],     pal, b0h);
                mma_bf16(oacc[2 * jp + 1], pah, b1h);
                mma_bf16(oacc[2 * jp + 1], pah, b1l);
                mma_bf16(oacc[2 * jp + 1], pal, b1h);
            }
        }
    }

    // ---- finalize: divide by l, split-store ----
    float il0 = 1.f / sl0, il1 = 1.f / sl1;
    size_t r0off = (rowbase + q0 + wrow + (lane >> 2)) * CC + h * HD + (lane & 3) * 2;
    #pragma unroll
    for (int j = 0; j < 16; j++) {
        size_t o0 = r0off + j * 8;
        size_t o1 = o0 + (size_t)8 * CC;
        split_store(oacc[j][0] * il0, &oh_g[o0],     &ol_g[o0]);
        split_store(oacc[j][1] * il0, &oh_g[o0 + 1], &ol_g[o0 + 1]);
        split_store(oacc[j][2] * il1, &oh_g[o1],     &ol_g[o1]);
        split_store(oacc[j][3] * il1, &oh_g[o1 + 1], &ol_g[o1 + 1]);
    }
}

// ------------------------------------------------------------------
// host launcher
// ------------------------------------------------------------------
extern "C" void kernel_launch(void* const* d_in, const int* in_sizes, int n_in,
                              void* d_out, int out_size) {
    const float* x     = (const float*)d_in[0];
    const float* Wq    = (const float*)d_in[1];
    const float* Wk    = (const float*)d_in[2];
    const float* Wv    = (const float*)d_in[3];
    const float* Wp    = (const float*)d_in[4];
    const float* bp    = (const float*)d_in[5];
    const float* W1    = (const float*)d_in[6];
    const float* b1    = (const float*)d_in[7];
    const float* W2    = (const float*)d_in[8];
    const float* b2    = (const float*)d_in[9];
    const float* g1    = (const float*)d_in[10];
    const float* beta1 = (const float*)d_in[11];
    const float* g2    = (const float*)d_in[12];
    const float* beta2 = (const float*)d_in[13];
    float* out = (float*)d_out;

    __nv_bfloat16 *h1h, *h1l, *qvh, *qvl, *ath, *atl, *h2h, *h2l, *fh, *fl;
    __nv_bfloat16 *wqh, *wql, *wph, *wpl, *w1h, *w1l, *w2h, *w2l;
    float *x1;
    cudaGetSymbolAddress((void**)&h1h, g_h1h);  cudaGetSymbolAddress((void**)&h1l, g_h1l);
    cudaGetSymbolAddress((void**)&qvh, g_qkvh); cudaGetSymbolAddress((void**)&qvl, g_qkvl);
    cudaGetSymbolAddress((void**)&ath, g_ath);  cudaGetSymbolAddress((void**)&atl, g_atl);
    cudaGetSymbolAddress((void**)&x1,  g_x1);
    cudaGetSymbolAddress((void**)&h2h, g_h2h);  cudaGetSymbolAddress((void**)&h2l, g_h2l);
    cudaGetSymbolAddress((void**)&fh,  g_fh);   cudaGetSymbolAddress((void**)&fl,  g_fl);
    cudaGetSymbolAddress((void**)&wqh, g_wqh);  cudaGetSymbolAddress((void**)&wql, g_wql);
    cudaGetSymbolAddress((void**)&wph, g_wph);  cudaGetSymbolAddress((void**)&wpl, g_wpl);
    cudaGetSymbolAddress((void**)&w1h, g_w1h);  cudaGetSymbolAddress((void**)&w1l, g_w1l);
    cudaGetSymbolAddress((void**)&w2h, g_w2h);  cudaGetSymbolAddress((void**)&w2l, g_w2l);

    cudaFuncSetAttribute(attention_mma,
                         cudaFuncAttributeMaxDynamicSharedMemorySize, ATTN_SMEM);
    cudaFuncSetAttribute(gemm_mma<false, false, false, true>,
                         cudaFuncAttributeMaxDynamicSharedMemorySize, GEMM_SMEM);
    cudaFuncSetAttribute(gemm_mma<true, true, false, false>,
                         cudaFuncAttributeMaxDynamicSharedMemorySize, GEMM_SMEM);
    cudaFuncSetAttribute(gemm_mma<true, false, true, true>,
                         cudaFuncAttributeMaxDynamicSharedMemorySize, GEMM_SMEM);

    dim3 tb(32, 8);
    // weight prep: transpose + hi/lo split
    for (int s = 0; s < 3; s++) {
        const float* Ws = (s == 0) ? Wq : (s == 1) ? Wk : Wv;
        transpose_split_kernel<<<dim3(HD / 32, CC / 32, HH), tb>>>(
            Ws, wqh + (size_t)s * CC * CC, wql + (size_t)s * CC * CC,
            HD, (size_t)CC * HD, HD, CC);
    }
    transpose_split_kernel<<<dim3(CC / 32, CC / 32, 1), tb>>>(Wp, wph, wpl, CC, 0, CC, CC);
    transpose_split_kernel<<<dim3(C4 / 32, CC / 32, 1), tb>>>(W1, w1h, w1l, C4, 0, C4, CC);
    transpose_split_kernel<<<dim3(CC / 32, C4 / 32, 1), tb>>>(W2, w2h, w2l, CC, 0, CC, C4);

    // 1. LN1 -> h1 (bf16 hi/lo)
    ln_kernel<<<NTOK, 256>>>(x, g1, beta1, h1h, h1l);
    // 2. QKV GEMM -> qkv (bf16 hi/lo split output)
    gemm_mma<false, false, false, true><<<dim3(QKVN / 128, NTOK / 128), 256, GEMM_SMEM>>>(
        h1h, h1l, wqh, wql, nullptr, nullptr, nullptr, qvh, qvl, QKVN, CC);
    // 3. tensor-core flash attention -> attn (bf16 hi/lo)
    attention_mma<<<dim3(TT / 128, BB * HH), 256, ATTN_SMEM>>>(qvh, qvl, ath, atl);
    // 4. proj: x1 = x + attn @ Wp + bp   (fp32)
    gemm_mma<true, true, false, false><<<dim3(CC / 128, NTOK / 128), 256, GEMM_SMEM>>>(
        ath, atl, wph, wpl, bp, x, x1, nullptr, nullptr, CC, CC);
    // 5. LN2 -> h2
    ln_kernel<<<NTOK, 256>>>(x1, g2, beta2, h2h, h2l);
    // 6. FFN1: f = gelu(h2 @ W1 + b1) -> bf16 hi/lo
    gemm_mma<true, false, true, true><<<dim3(C4 / 128, NTOK / 128), 256, GEMM_SMEM>>>(
        h2h, h2l, w1h, w1l, b1, nullptr, nullptr, fh, fl, C4, CC);
    // 7. FFN2: out = x1 + f @ W2 + b2   (fp32)
    gemm_mma<true, true, false, false><<<dim3(CC / 128, NTOK / 128), 256, GEMM_SMEM>>>(
        fh, fl, w2h, w2l, b2, x1, out, nullptr, nullptr, CC, C4);
}